// round 1
// baseline (speedup 1.0000x reference)
#include <cuda_runtime.h>

// Problem dims
#define HH 128
#define WD 128
#define BB 8
#define DD 512
#define M_TOTAL (HH * WD * BB)   // 131072 rows
#define N_TOTAL DD               // 512
#define K_TOTAL DD               // 512

// Scratch for Y = X @ W^T + b  (131072 x 512 fp32 = 256 MiB)
__device__ float g_y[(size_t)M_TOTAL * N_TOTAL];

// ---------------------------------------------------------------------------
// SGEMM: C[m,n] = sum_k A[m,k] * W[n,k] + bias[n]
// A: [M, K] row-major (x flattened), W: [N, K] row-major (Wlin[e,d])
// Tiles: BM=128, BN=128, BK=8, 256 threads, 8x8 per thread.
// ---------------------------------------------------------------------------
__global__ __launch_bounds__(256) void gemm_fp32_kernel(
    const float* __restrict__ A,
    const float* __restrict__ W,
    const float* __restrict__ bias)
{
    __shared__ float As[8][128];
    __shared__ float Bs[8][128];

    const int tid = threadIdx.x;
    const int m0 = blockIdx.y * 128;
    const int n0 = blockIdx.x * 128;

    const int lrow = tid >> 1;           // 0..127
    const int lcol = (tid & 1) * 4;      // 0 or 4

    const int tm = (tid >> 4) * 8;       // 0..120
    const int tn = (tid & 15) * 8;       // 0..120

    const float* Aptr = A + (size_t)(m0 + lrow) * K_TOTAL + lcol;
    const float* Wptr = W + (size_t)(n0 + lrow) * K_TOTAL + lcol;

    float acc[8][8];
#pragma unroll
    for (int i = 0; i < 8; ++i)
#pragma unroll
        for (int j = 0; j < 8; ++j) acc[i][j] = 0.0f;

    for (int k0 = 0; k0 < K_TOTAL; k0 += 8) {
        float4 a4 = *(const float4*)(Aptr + k0);
        float4 w4 = *(const float4*)(Wptr + k0);

        __syncthreads();   // previous tile fully consumed
        As[lcol + 0][lrow] = a4.x;
        As[lcol + 1][lrow] = a4.y;
        As[lcol + 2][lrow] = a4.z;
        As[lcol + 3][lrow] = a4.w;
        Bs[lcol + 0][lrow] = w4.x;
        Bs[lcol + 1][lrow] = w4.y;
        Bs[lcol + 2][lrow] = w4.z;
        Bs[lcol + 3][lrow] = w4.w;
        __syncthreads();   // tile ready

#pragma unroll
        for (int k = 0; k < 8; ++k) {
            float ar[8], br[8];
#pragma unroll
            for (int i = 0; i < 8; ++i) ar[i] = As[k][tm + i];
#pragma unroll
            for (int j = 0; j < 8; ++j) br[j] = Bs[k][tn + j];
#pragma unroll
            for (int i = 0; i < 8; ++i)
#pragma unroll
                for (int j = 0; j < 8; ++j)
                    acc[i][j] += ar[i] * br[j];
        }
    }

    // epilogue: add bias, write Y
    float bv[8];
#pragma unroll
    for (int j = 0; j < 8; ++j) bv[j] = bias[n0 + tn + j];

#pragma unroll
    for (int i = 0; i < 8; ++i) {
        float* cp = g_y + (size_t)(m0 + tm + i) * N_TOTAL + n0 + tn;
#pragma unroll
        for (int j = 0; j < 8; j += 4) {
            float4 v;
            v.x = acc[i][j + 0] + bv[j + 0];
            v.y = acc[i][j + 1] + bv[j + 1];
            v.z = acc[i][j + 2] + bv[j + 2];
            v.w = acc[i][j + 3] + bv[j + 3];
            *(float4*)(cp + j) = v;
        }
    }
}

// ---------------------------------------------------------------------------
// Bidirectional LIF scan along w (128 steps each direction) per (h,b,e) lane.
// y row index for step w: l = h*WD + w; flat row = l*BB + b; element e.
// out[l, b, e] = s_fwd(w) + s_bwd(w)   (s_bwd already "un-reversed" by index)
// Spikes are packed into bit registers; one pass writes the final output.
// ---------------------------------------------------------------------------
__global__ __launch_bounds__(256) void lif_scan_kernel(float* __restrict__ out)
{
    const int g = blockIdx.x * 256 + threadIdx.x;    // 0 .. 128*8*512-1
    const int e = g & (DD - 1);
    const int b = (g >> 9) & (BB - 1);
    const int h = g >> 12;

    const size_t base = ((size_t)h * WD * BB + b) * DD + e;  // w = 0 row
    const float* yp = g_y + base;
    const size_t wstride = (size_t)BB * DD;                  // 4096

    unsigned fw[4] = {0u, 0u, 0u, 0u};
    unsigned bw[4] = {0u, 0u, 0u, 0u};

    // forward scan (channel 0)
    {
        float v = 0.0f;
#pragma unroll 8
        for (int w = 0; w < WD; ++w) {
            float yt = yp[(size_t)w * wstride];
            v = v + (yt - v) * 0.5f;     // v += (x - v)/TAU, TAU=2
            if (v - 1.0f >= 0.0f) {      // atan_spike(v - V_TH)
                fw[w >> 5] |= 1u << (w & 31);
                v = 0.0f;                // (1 - s) * v
            }
        }
    }

    // backward scan (channel 1, sequence reversed along w)
    {
        float v = 0.0f;
#pragma unroll 8
        for (int w = WD - 1; w >= 0; --w) {
            float yt = yp[(size_t)w * wstride];
            v = v + (yt - v) * 0.5f;
            if (v - 1.0f >= 0.0f) {
                bw[w >> 5] |= 1u << (w & 31);
                v = 0.0f;
            }
        }
    }

    float* op = out + base;
#pragma unroll 8
    for (int w = 0; w < WD; ++w) {
        float s = (float)(((fw[w >> 5] >> (w & 31)) & 1u) +
                          ((bw[w >> 5] >> (w & 31)) & 1u));
        op[(size_t)w * wstride] = s;
    }
}

extern "C" void kernel_launch(void* const* d_in, const int* in_sizes, int n_in,
                              void* d_out, int out_size)
{
    const float* x    = (const float*)d_in[0];   // (16384, 8, 512) fp32
    const float* Wlin = (const float*)d_in[1];   // (512, 512) fp32
    const float* blin = (const float*)d_in[2];   // (512,) fp32
    float* out = (float*)d_out;                  // (16384, 8, 512) fp32

    dim3 ggrid(N_TOTAL / 128, M_TOTAL / 128);    // (4, 1024)
    gemm_fp32_kernel<<<ggrid, 256>>>(x, Wlin, blin);

    lif_scan_kernel<<<(HH * BB * DD) / 256, 256>>>(out);
}

// round 5
// speedup vs baseline: 1.3993x; 1.3993x over previous
#include <cuda_runtime.h>
#include <cuda_bf16.h>
#include <cstdint>

// Problem dims
#define HH 128
#define WD 128
#define BB 8
#define DD 512
#define M_TOTAL (HH * WD * BB)   // 131072 rows
#define GUARD 5e-5f

// Scratch for Y = X @ W^T + b  (131072 x 512 fp32 = 256 MiB)
__device__ float g_y[(size_t)M_TOTAL * DD];
__device__ unsigned g_flag_list[HH * BB * DD];   // flagged column ids
__device__ unsigned g_flag_cnt;

// ---------------------------------------------------------------------------
// MMA macros: m16n8k16 bf16 -> fp32.  ZERO starts a fresh chain (c = 0),
// ACC chains c through the tensor core (only used within one 32-k chunk).
// ---------------------------------------------------------------------------
#define MMA_ZERO(d, a0, a1, a2, a3, b0, b1)                                  \
    asm volatile(                                                            \
        "mma.sync.aligned.m16n8k16.row.col.f32.bf16.bf16.f32 "              \
        "{%0,%1,%2,%3}, {%4,%5,%6,%7}, {%8,%9}, {%10,%10,%10,%10};"         \
        : "=f"((d)[0]), "=f"((d)[1]), "=f"((d)[2]), "=f"((d)[3])             \
        : "r"(a0), "r"(a1), "r"(a2), "r"(a3), "r"(b0), "r"(b1), "f"(0.0f))

#define MMA_ACC(d, a0, a1, a2, a3, b0, b1)                                   \
    asm volatile(                                                            \
        "mma.sync.aligned.m16n8k16.row.col.f32.bf16.bf16.f32 "              \
        "{%0,%1,%2,%3}, {%4,%5,%6,%7}, {%8,%9}, {%0,%1,%2,%3};"             \
        : "+f"((d)[0]), "+f"((d)[1]), "+f"((d)[2]), "+f"((d)[3])             \
        : "r"(a0), "r"(a1), "r"(a2), "r"(a3), "r"(b0), "r"(b1))

#define SSTR 136                       // uint32 stride per kp row (conflict-free)
#define LVL  (16 * SSTR)               // one level buffer (16 kp x 128 rows)

// ---------------------------------------------------------------------------
// GEMM: Y[m,n] = sum_k X[m,k]*Wlin[n,k] + bias[n]
// bf16 2-level split, 3 passes (00, 01, 10); per 32-k chunk: fresh c=0 chain
// of 6 mma, then FADD into fp32 register master (avoids TC RZ-chain bias).
// CTA tile 128x128, BK=32, 8 warps (2M x 4N), warp tile 64x32.
// ---------------------------------------------------------------------------
__global__ __launch_bounds__(256, 1) void gemm_tc_kernel(
    const float* __restrict__ A,
    const float* __restrict__ Wl,
    const float* __restrict__ bias)
{
    __shared__ uint32_t smem[4 * LVL];   // A0, A1, W0, W1
    uint32_t* As0 = smem;
    uint32_t* As1 = smem + LVL;
    uint32_t* Ws0 = smem + 2 * LVL;
    uint32_t* Ws1 = smem + 3 * LVL;

    const int tid  = threadIdx.x;
    const int lane = tid & 31;
    const int wid  = tid >> 5;
    const int wm   = wid >> 2;        // 0..1 (M)
    const int wn   = wid & 3;         // 0..3 (N)

    const int m0 = blockIdx.y << 7;
    const int n0 = blockIdx.x << 7;

    if (blockIdx.x == 0 && blockIdx.y == 0 && tid == 0) g_flag_cnt = 0;

    // producer assignment: each thread loads 16 floats of A and W per iter
    const int row = tid >> 1;                 // 0..127
    const int kq  = (tid & 1) << 4;           // 0 or 16
    const float* ag = A  + (size_t)(m0 + row) * 512 + kq;
    const float* wg = Wl + (size_t)(n0 + row) * 512 + kq;

    float acc[4][4][4];
#pragma unroll
    for (int mt = 0; mt < 4; ++mt)
#pragma unroll
        for (int nt = 0; nt < 4; ++nt)
#pragma unroll
            for (int r = 0; r < 4; ++r) acc[mt][nt][r] = 0.0f;

    float4 pa[4], pw[4];
#pragma unroll
    for (int j = 0; j < 4; ++j) {
        pa[j] = ((const float4*)ag)[j];
        pw[j] = ((const float4*)wg)[j];
    }

    const int q = lane & 3;
    const int r = lane >> 2;

    for (int it = 0; it < 16; ++it) {
        // split2 + store current tile to smem (k pairs)
        const float* av = (const float*)pa;
        const float* wv = (const float*)pw;
#pragma unroll
        for (int j = 0; j < 8; ++j) {
            const int kp = (kq >> 1) + j;
            float x0 = av[2 * j], x1 = av[2 * j + 1];
            __nv_bfloat16 h0 = __float2bfloat16_rn(x0);
            __nv_bfloat16 h1 = __float2bfloat16_rn(x1);
            __nv_bfloat16 l0 = __float2bfloat16_rn(x0 - __bfloat162float(h0));
            __nv_bfloat16 l1 = __float2bfloat16_rn(x1 - __bfloat162float(h1));
            As0[kp * SSTR + row] = (uint32_t)__bfloat16_as_ushort(h0) |
                                   ((uint32_t)__bfloat16_as_ushort(h1) << 16);
            As1[kp * SSTR + row] = (uint32_t)__bfloat16_as_ushort(l0) |
                                   ((uint32_t)__bfloat16_as_ushort(l1) << 16);
            x0 = wv[2 * j]; x1 = wv[2 * j + 1];
            h0 = __float2bfloat16_rn(x0);
            h1 = __float2bfloat16_rn(x1);
            l0 = __float2bfloat16_rn(x0 - __bfloat162float(h0));
            l1 = __float2bfloat16_rn(x1 - __bfloat162float(h1));
            Ws0[kp * SSTR + row] = (uint32_t)__bfloat16_as_ushort(h0) |
                                   ((uint32_t)__bfloat16_as_ushort(h1) << 16);
            Ws1[kp * SSTR + row] = (uint32_t)__bfloat16_as_ushort(l0) |
                                   ((uint32_t)__bfloat16_as_ushort(l1) << 16);
        }
        __syncthreads();

        if (it < 15) {
            const float* an = ag + (it + 1) * 32;
            const float* wg2 = wg + (it + 1) * 32;
#pragma unroll
            for (int j = 0; j < 4; ++j) {
                pa[j] = ((const float4*)an)[j];
                pw[j] = ((const float4*)wg2)[j];
            }
        }

        // B fragments for both ksteps, both levels
        uint32_t bf[2][2][4][2];   // [level][ks][nt][half]
#pragma unroll
        for (int ks = 0; ks < 2; ++ks) {
            const int kb = ks * 8 + q;
#pragma unroll
            for (int nt = 0; nt < 4; ++nt) {
                const int col = (wn << 5) + (nt << 3) + r;
                bf[0][ks][nt][0] = Ws0[kb * SSTR + col];
                bf[0][ks][nt][1] = Ws0[(kb + 4) * SSTR + col];
                bf[1][ks][nt][0] = Ws1[kb * SSTR + col];
                bf[1][ks][nt][1] = Ws1[(kb + 4) * SSTR + col];
            }
        }

#pragma unroll
        for (int mt = 0; mt < 4; ++mt) {
            const int m = (wm << 6) + (mt << 4) + r;
            uint32_t af[2][2][4];  // [level][ks][4]
#pragma unroll
            for (int ks = 0; ks < 2; ++ks) {
                const int kb = ks * 8 + q;
                af[0][ks][0] = As0[kb * SSTR + m];
                af[0][ks][1] = As0[kb * SSTR + m + 8];
                af[0][ks][2] = As0[(kb + 4) * SSTR + m];
                af[0][ks][3] = As0[(kb + 4) * SSTR + m + 8];
                af[1][ks][0] = As1[kb * SSTR + m];
                af[1][ks][1] = As1[kb * SSTR + m + 8];
                af[1][ks][2] = As1[(kb + 4) * SSTR + m];
                af[1][ks][3] = As1[(kb + 4) * SSTR + m + 8];
            }
#pragma unroll
            for (int nt = 0; nt < 4; ++nt) {
                float d[4];
                // fresh chain; smallest-magnitude passes first
                MMA_ZERO(d, af[1][0][0], af[1][0][1], af[1][0][2], af[1][0][3],
                         bf[0][0][nt][0], bf[0][0][nt][1]);            // a1*b0 ks0
                MMA_ACC(d, af[1][1][0], af[1][1][1], af[1][1][2], af[1][1][3],
                        bf[0][1][nt][0], bf[0][1][nt][1]);             // a1*b0 ks1
                MMA_ACC(d, af[0][0][0], af[0][0][1], af[0][0][2], af[0][0][3],
                        bf[1][0][nt][0], bf[1][0][nt][1]);             // a0*b1 ks0
                MMA_ACC(d, af[0][1][0], af[0][1][1], af[0][1][2], af[0][1][3],
                        bf[1][1][nt][0], bf[1][1][nt][1]);             // a0*b1 ks1
                MMA_ACC(d, af[0][0][0], af[0][0][1], af[0][0][2], af[0][0][3],
                        bf[0][0][nt][0], bf[0][0][nt][1]);             // a0*b0 ks0
                MMA_ACC(d, af[0][1][0], af[0][1][1], af[0][1][2], af[0][1][3],
                        bf[0][1][nt][0], bf[0][1][nt][1]);             // a0*b0 ks1
                acc[mt][nt][0] += d[0];
                acc[mt][nt][1] += d[1];
                acc[mt][nt][2] += d[2];
                acc[mt][nt][3] += d[3];
            }
        }
        __syncthreads();
    }

    // epilogue: add bias, write Y
#pragma unroll
    for (int nt = 0; nt < 4; ++nt) {
        const int col = n0 + (wn << 5) + (nt << 3) + (q << 1);
        const float2 bb = *(const float2*)&bias[col];
#pragma unroll
        for (int mt = 0; mt < 4; ++mt) {
            const int rrow = m0 + (wm << 6) + (mt << 4) + r;
            float2 v0, v1;
            v0.x = acc[mt][nt][0] + bb.x;
            v0.y = acc[mt][nt][1] + bb.y;
            v1.x = acc[mt][nt][2] + bb.x;
            v1.y = acc[mt][nt][3] + bb.y;
            *(float2*)&g_y[(size_t)rrow * 512 + col]       = v0;
            *(float2*)&g_y[(size_t)(rrow + 8) * 512 + col] = v1;
        }
    }
}

// ---------------------------------------------------------------------------
// Bidirectional LIF scan + marginal-column flagging
// ---------------------------------------------------------------------------
__global__ __launch_bounds__(256) void lif_scan_kernel(float* __restrict__ out)
{
    const int g = blockIdx.x * 256 + threadIdx.x;
    const int e = g & (DD - 1);
    const int b = (g >> 9) & (BB - 1);
    const int h = g >> 12;

    const size_t base = ((size_t)h * WD * BB + b) * DD + e;
    const float* yp = g_y + base;
    const size_t wstride = (size_t)BB * DD;

    unsigned fw[4] = {0u, 0u, 0u, 0u};
    unsigned bw[4] = {0u, 0u, 0u, 0u};
    bool flag = false;

    {
        float v = 0.0f;
#pragma unroll 8
        for (int w = 0; w < WD; ++w) {
            float yt = yp[(size_t)w * wstride];
            v = v + (yt - v) * 0.5f;
            flag |= (fabsf(v - 1.0f) < GUARD);
            if (v - 1.0f >= 0.0f) {
                fw[w >> 5] |= 1u << (w & 31);
                v = 0.0f;
            }
        }
    }
    {
        float v = 0.0f;
#pragma unroll 8
        for (int w = WD - 1; w >= 0; --w) {
            float yt = yp[(size_t)w * wstride];
            v = v + (yt - v) * 0.5f;
            flag |= (fabsf(v - 1.0f) < GUARD);
            if (v - 1.0f >= 0.0f) {
                bw[w >> 5] |= 1u << (w & 31);
                v = 0.0f;
            }
        }
    }

    float* op = out + base;
#pragma unroll 8
    for (int w = 0; w < WD; ++w) {
        float s = (float)(((fw[w >> 5] >> (w & 31)) & 1u) +
                          ((bw[w >> 5] >> (w & 31)) & 1u));
        op[(size_t)w * wstride] = s;
    }

    if (flag) {
        unsigned idx = atomicAdd(&g_flag_cnt, 1u);
        g_flag_list[idx] = (unsigned)g;
    }
}

// ---------------------------------------------------------------------------
// Correction: for flagged columns recompute y exactly (ascending-k fp32 FMA,
// bit-identical to the fp32 reference path), redo both scans, overwrite out.
// One warp per column.
// ---------------------------------------------------------------------------
__global__ __launch_bounds__(256) void correct_kernel(
    const float* __restrict__ x,
    const float* __restrict__ Wl,
    const float* __restrict__ bias,
    float* __restrict__ out)
{
    __shared__ float wrow[8][512];
    __shared__ float ybuf[8][128];
    const int wid  = threadIdx.x >> 5;
    const int lane = threadIdx.x & 31;
    const unsigned gw = blockIdx.x * 8 + wid;
    const unsigned cnt = *(volatile unsigned*)&g_flag_cnt;
    const unsigned stride = gridDim.x * 8;

    for (unsigned i = gw; i < cnt; i += stride) {
        const unsigned g = g_flag_list[i];
        const int e = g & (DD - 1);
        const int b = (g >> 9) & (BB - 1);
        const int h = g >> 12;

        const float4* wr = (const float4*)(Wl + (size_t)e * 512);
#pragma unroll
        for (int j = 0; j < 4; ++j)
            ((float4*)wrow[wid])[lane + 32 * j] = wr[lane + 32 * j];
        __syncwarp();

        const float be = bias[e];
#pragma unroll
        for (int t = 0; t < 4; ++t) {
            const int w = t * 32 + lane;
            const float4* x4 = (const float4*)(x +
                ((size_t)(h * WD + w) * BB + b) * 512);
            float acc = 0.0f;
            for (int k4 = 0; k4 < 128; ++k4) {
                float4 xv = x4[k4];
                const float* ww = &wrow[wid][k4 * 4];
                acc = fmaf(xv.x, ww[0], acc);
                acc = fmaf(xv.y, ww[1], acc);
                acc = fmaf(xv.z, ww[2], acc);
                acc = fmaf(xv.w, ww[3], acc);
            }
            ybuf[wid][w] = acc + be;
        }
        __syncwarp();

        unsigned fw[4] = {0u, 0u, 0u, 0u};
        unsigned bw[4] = {0u, 0u, 0u, 0u};
        {
            float v = 0.0f;
            for (int w = 0; w < WD; ++w) {
                float yt = ybuf[wid][w];
                v = v + (yt - v) * 0.5f;
                if (v - 1.0f >= 0.0f) { fw[w >> 5] |= 1u << (w & 31); v = 0.0f; }
            }
        }
        {
            float v = 0.0f;
            for (int w = WD - 1; w >= 0; --w) {
                float yt = ybuf[wid][w];
                v = v + (yt - v) * 0.5f;
                if (v - 1.0f >= 0.0f) { bw[w >> 5] |= 1u << (w & 31); v = 0.0f; }
            }
        }
#pragma unroll
        for (int t = 0; t < 4; ++t) {
            const int w = t * 32 + lane;
            float s = (float)(((fw[w >> 5] >> (w & 31)) & 1u) +
                              ((bw[w >> 5] >> (w & 31)) & 1u));
            out[((size_t)(h * WD + w) * BB + b) * 512 + e] = s;
        }
        __syncwarp();
    }
}

extern "C" void kernel_launch(void* const* d_in, const int* in_sizes, int n_in,
                              void* d_out, int out_size)
{
    const float* x    = (const float*)d_in[0];   // (16384, 8, 512) fp32
    const float* Wlin = (const float*)d_in[1];   // (512, 512) fp32
    const float* blin = (const float*)d_in[2];   // (512,) fp32
    float* out = (float*)d_out;

    dim3 ggrid(4, 1024);   // N/128, M/128
    gemm_tc_kernel<<<ggrid, 256>>>(x, Wlin, blin);

    lif_scan_kernel<<<(HH * BB * DD) / 256, 256>>>(out);

    correct_kernel<<<256, 256>>>(x, Wlin, blin, out);
}